// round 6
// baseline (speedup 1.0000x reference)
#include <cuda_runtime.h>
#include <cstdint>

// PQLayer forward on GB300 (sm_103a) — v6: b-major idx scratch so kernel B's
// idx read is one contiguous 64B span per warp (v5 read 64 scattered lines
// -> latency-bound 19us). A unchanged otherwise.
//
// codes = stop_gradient(hard - soft) + soft == hard (one-hot) numerically.

#define BB 16384
#define MM 64
#define KK 256
#define DD 8
#define FEAT (MM * DD)          // 512
#define CHUNK_B 256             // b per block in kernel A (8 warps x 32)

using u64 = unsigned long long;

__device__ uint8_t g_idx[(size_t)BB * MM];   // scratch: idx[b][m], 1 MB (b-major)

__device__ __forceinline__ u64 pack2(float lo, float hi) {
    u64 r;
    uint32_t a = __float_as_uint(lo), b = __float_as_uint(hi);
    asm("mov.b64 %0, {%1, %2};" : "=l"(r) : "r"(a), "r"(b));
    return r;
}

__device__ __forceinline__ void unpack2(u64 v, float& lo, float& hi) {
    uint32_t a, b;
    asm("mov.b64 {%0, %1}, %2;" : "=r"(a), "=r"(b) : "l"(v));
    lo = __uint_as_float(a);
    hi = __uint_as_float(b);
}

// Packed dual fp32 FMA (Blackwell FFMA2): IEEE fp32 per lane.
__device__ __forceinline__ u64 fma2(u64 a, u64 b, u64 c) {
    u64 r;
    asm("fma.rn.f32x2 %0, %1, %2, %3;" : "=l"(r) : "l"(a), "l"(b), "l"(c));
    return r;
}

// ---------------------------------------------------------------------------
// Kernel A: per-subspace argmax, fused one-hot row stream (coalesced,
// single-touch STG.128) + 1-byte idx (b-major) for kernel B.
// ---------------------------------------------------------------------------
__global__ void __launch_bounds__(256)
pq_argmax_onehot(const float* __restrict__ x, const float* __restrict__ C,
                 float* __restrict__ codes)
{
    const int m    = blockIdx.x;
    const int tid  = threadIdx.x;
    const int lane = tid & 31;
    const int w    = tid >> 5;

    // cpk[j*8 + d] = { C[m][2j][d], C[m][2j+1][d] }  (k-pair packed, 8 KB)
    __shared__ __align__(16) u64 cpk[128 * 8];

    {
        const float4* C4 = reinterpret_cast<const float4*>(C) + (size_t)m * (KK * 2);
#pragma unroll
        for (int q = tid; q < KK * 2; q += 256) {
            float4 f = C4[q];
            const int k = q >> 1, h = (q & 1) * 4;
            const int j = k >> 1, half = k & 1;
            float vals[4] = {f.x, f.y, f.z, f.w};
#pragma unroll
            for (int dd = 0; dd < 4; dd++)
                reinterpret_cast<uint32_t*>(&cpk[j * 8 + h + dd])[half] =
                    __float_as_uint(vals[dd]);
        }
    }
    __syncthreads();

    const int b0w = blockIdx.y * CHUNK_B + w * 32;   // warp's first b
    const int b   = b0w + lane;

    // ---- load x[b, m*8 .. m*8+8], duplicate-pack for f32x2 ----
    const float4* x4 = reinterpret_cast<const float4*>(x) + (size_t)b * (FEAT / 4) + m * 2;
    const float4 xa = x4[0];
    const float4 xb = x4[1];
    u64 xp[8];
    xp[0] = pack2(xa.x, xa.x); xp[1] = pack2(xa.y, xa.y);
    xp[2] = pack2(xa.z, xa.z); xp[3] = pack2(xa.w, xa.w);
    xp[4] = pack2(xb.x, xb.x); xp[5] = pack2(xb.y, xb.y);
    xp[6] = pack2(xb.z, xb.z); xp[7] = pack2(xb.w, xb.w);

    // ---- argmax over 256 codewords: 128 packed k-pairs ----
    float bv = -3.402823466e+38f;
    int   bk = 0;
#pragma unroll 8
    for (int j = 0; j < 128; j++) {
        const ulonglong2* cj = reinterpret_cast<const ulonglong2*>(&cpk[j * 8]);
        ulonglong2 c01 = cj[0], c23 = cj[1], c45 = cj[2], c67 = cj[3];
        u64 acc = 0ull;                 // {+0, +0}; d-sequential fp32 accumulation
        acc = fma2(c01.x, xp[0], acc);
        acc = fma2(c01.y, xp[1], acc);
        acc = fma2(c23.x, xp[2], acc);
        acc = fma2(c23.y, xp[3], acc);
        acc = fma2(c45.x, xp[4], acc);
        acc = fma2(c45.y, xp[5], acc);
        acc = fma2(c67.x, xp[6], acc);
        acc = fma2(c67.y, xp[7], acc);
        float lo, hi;
        unpack2(acc, lo, hi);
        if (lo > bv) { bv = lo; bk = 2 * j; }       // strict >: lowest k wins ties
        if (hi > bv) { bv = hi; bk = 2 * j + 1; }
    }

    // ---- write idx byte, b-major (so kernel B reads 64B contiguous) ----
    g_idx[(size_t)b * MM + m] = (uint8_t)bk;

    // ---- fused one-hot stream: 32 rows, each written ONCE, coalesced ----
    // Row r belongs to b0w+r; its winner lives in lane r -> broadcast via shfl.
    {
        float4* crow = reinterpret_cast<float4*>(codes) +
                       ((size_t)b0w * MM + m) * (KK / 4) + lane;
        const int k0 = 4 * lane;          // this lane's first float4 covers k0..k0+3
        const int k1 = 128 + 4 * lane;    // second float4 covers k1..k1+3
#pragma unroll 8
        for (int r = 0; r < 32; r++) {
            const int ok = __shfl_sync(0xffffffffu, bk, r);
            float4 v0, v1;
            v0.x = (k0 + 0 == ok) ? 1.f : 0.f;
            v0.y = (k0 + 1 == ok) ? 1.f : 0.f;
            v0.z = (k0 + 2 == ok) ? 1.f : 0.f;
            v0.w = (k0 + 3 == ok) ? 1.f : 0.f;
            v1.x = (k1 + 0 == ok) ? 1.f : 0.f;
            v1.y = (k1 + 1 == ok) ? 1.f : 0.f;
            v1.z = (k1 + 2 == ok) ? 1.f : 0.f;
            v1.w = (k1 + 3 == ok) ? 1.f : 0.f;
            __stcs(crow, v0);             // k[4*lane .. 4*lane+4)
            __stcs(crow + 32, v1);        // k[128+4*lane .. )
            crow += MM * (KK / 4);        // next b, same m
        }
    }
}

// ---------------------------------------------------------------------------
// Kernel B: b-major. Coalesced idx read (64B/warp), codeword gather,
// contiguous x_hat rows. 2 b's per warp -> 4 independent chains per lane.
// ---------------------------------------------------------------------------
__global__ void __launch_bounds__(256)
pq_xhat(const float* __restrict__ C, float* __restrict__ xhat)
{
    const int lane = threadIdx.x & 31;
    const int w    = threadIdx.x >> 5;
    const int bA   = blockIdx.x * 16 + w * 2;    // warp owns b pair {bA, bA+1}
    const int bB   = bA + 1;

    // idx reads: contiguous 64B per b (L2-hot, 2 sectors), all issued up front
    const uint8_t* rA = g_idx + (size_t)bA * MM;
    const uint8_t* rB = g_idx + (size_t)bB * MM;
    const int kA0 = rA[lane];
    const int kA1 = rA[lane + 32];
    const int kB0 = rB[lane];
    const int kB1 = rB[lane + 32];

    // ---- gather selected codewords (C is 2 MB -> L2-resident), MLP=4 ----
    const float4* C4 = reinterpret_cast<const float4*>(C);
    const size_t iA0 = ((size_t)lane        * KK + kA0) * 2;
    const size_t iA1 = ((size_t)(lane + 32) * KK + kA1) * 2;
    const size_t iB0 = ((size_t)lane        * KK + kB0) * 2;
    const size_t iB1 = ((size_t)(lane + 32) * KK + kB1) * 2;
    const float4 a00 = __ldg(&C4[iA0]),     a01 = __ldg(&C4[iA0 + 1]);
    const float4 a10 = __ldg(&C4[iA1]),     a11 = __ldg(&C4[iA1 + 1]);
    const float4 b00 = __ldg(&C4[iB0]),     b01 = __ldg(&C4[iB0 + 1]);
    const float4 b10 = __ldg(&C4[iB1]),     b11 = __ldg(&C4[iB1 + 1]);

    // ---- x_hat rows: contiguous across the warp (1 KB per instr) ----
    float4* xhA = reinterpret_cast<float4*>(xhat) + (size_t)bA * (FEAT / 4);
    float4* xhB = reinterpret_cast<float4*>(xhat) + (size_t)bB * (FEAT / 4);
    __stcs(&xhA[lane * 2],            a00);
    __stcs(&xhA[lane * 2 + 1],        a01);
    __stcs(&xhA[(lane + 32) * 2],     a10);
    __stcs(&xhA[(lane + 32) * 2 + 1], a11);
    __stcs(&xhB[lane * 2],            b00);
    __stcs(&xhB[lane * 2 + 1],        b01);
    __stcs(&xhB[(lane + 32) * 2],     b10);
    __stcs(&xhB[(lane + 32) * 2 + 1], b11);
}

extern "C" void kernel_launch(void* const* d_in, const int* in_sizes, int n_in,
                              void* d_out, int out_size)
{
    const float* x = (const float*)d_in[0];
    const float* C = (const float*)d_in[1];
    if (n_in >= 2 && in_sizes[0] == MM * KK * DD && in_sizes[1] == BB * FEAT) {
        x = (const float*)d_in[1];
        C = (const float*)d_in[0];
    }

    const long XHAT_N  = (long)BB * FEAT;        // 8,388,608
    const long CODES_N = (long)BB * MM * KK;     // 268,435,456

    float* xhat  = nullptr;
    float* codes = nullptr;
    if ((long)out_size >= XHAT_N + CODES_N) {
        xhat  = (float*)d_out;
        codes = (float*)d_out + XHAT_N;
    } else if ((long)out_size == CODES_N) {
        codes = (float*)d_out;
    } else {
        xhat = (float*)d_out;
    }

    dim3 gridA(MM, BB / CHUNK_B);                // (64, 64)
    pq_argmax_onehot<<<gridA, 256>>>(x, C, codes);
    if (xhat) pq_xhat<<<BB / 16, 256>>>(C, xhat);   // 1024 blocks, 2 b's/warp
}

// round 7
// speedup vs baseline: 1.5791x; 1.5791x over previous
#include <cuda_runtime.h>
#include <cstdint>

// PQLayer forward on GB300 (sm_103a) — v7: single kernel. v5's kernel A
// (m-major, fused coalesced one-hot stream) + direct x_hat writes: each lane's
// x_hat span is one aligned 32B sector -> no RMW, and default-cached stores
// merge in L2. Kernel B and the idx scratch are gone.
//
// codes = stop_gradient(hard - soft) + soft == hard (one-hot) numerically.

#define BB 16384
#define MM 64
#define KK 256
#define DD 8
#define FEAT (MM * DD)          // 512
#define CHUNK_B 256             // b per block (8 warps x 32)

using u64 = unsigned long long;

__device__ __forceinline__ u64 pack2(float lo, float hi) {
    u64 r;
    uint32_t a = __float_as_uint(lo), b = __float_as_uint(hi);
    asm("mov.b64 %0, {%1, %2};" : "=l"(r) : "r"(a), "r"(b));
    return r;
}

__device__ __forceinline__ void unpack2(u64 v, float& lo, float& hi) {
    uint32_t a, b;
    asm("mov.b64 {%0, %1}, %2;" : "=r"(a), "=r"(b) : "l"(v));
    lo = __uint_as_float(a);
    hi = __uint_as_float(b);
}

// Packed dual fp32 FMA (Blackwell FFMA2): IEEE fp32 per lane.
__device__ __forceinline__ u64 fma2(u64 a, u64 b, u64 c) {
    u64 r;
    asm("fma.rn.f32x2 %0, %1, %2, %3;" : "=l"(r) : "l"(a), "l"(b), "l"(c));
    return r;
}

__global__ void __launch_bounds__(256)
pq_forward_v7(const float* __restrict__ x, const float* __restrict__ C,
              float* __restrict__ xhat, float* __restrict__ codes)
{
    const int m    = blockIdx.x;
    const int tid  = threadIdx.x;
    const int lane = tid & 31;
    const int w    = tid >> 5;

    // cpk[j*8 + d] = { C[m][2j][d], C[m][2j+1][d] }  (k-pair packed, 8 KB)
    __shared__ __align__(16) u64    cpk[128 * 8];
    __shared__ __align__(16) float4 craw[KK * 2];    // raw copy for x_hat write

    {
        const float4* C4 = reinterpret_cast<const float4*>(C) + (size_t)m * (KK * 2);
#pragma unroll
        for (int q = tid; q < KK * 2; q += 256) {
            float4 f = C4[q];
            craw[q] = f;
            const int k = q >> 1, h = (q & 1) * 4;
            const int j = k >> 1, half = k & 1;
            float vals[4] = {f.x, f.y, f.z, f.w};
#pragma unroll
            for (int dd = 0; dd < 4; dd++)
                reinterpret_cast<uint32_t*>(&cpk[j * 8 + h + dd])[half] =
                    __float_as_uint(vals[dd]);
        }
    }
    __syncthreads();

    const int b0w = blockIdx.y * CHUNK_B + w * 32;   // warp's first b
    const int b   = b0w + lane;

    // ---- load x[b, m*8 .. m*8+8], duplicate-pack for f32x2 ----
    const float4* x4 = reinterpret_cast<const float4*>(x) + (size_t)b * (FEAT / 4) + m * 2;
    const float4 xa = x4[0];
    const float4 xb = x4[1];
    u64 xp[8];
    xp[0] = pack2(xa.x, xa.x); xp[1] = pack2(xa.y, xa.y);
    xp[2] = pack2(xa.z, xa.z); xp[3] = pack2(xa.w, xa.w);
    xp[4] = pack2(xb.x, xb.x); xp[5] = pack2(xb.y, xb.y);
    xp[6] = pack2(xb.z, xb.z); xp[7] = pack2(xb.w, xb.w);

    // ---- argmax over 256 codewords: 128 packed k-pairs ----
    float bv = -3.402823466e+38f;
    int   bk = 0;
#pragma unroll 8
    for (int j = 0; j < 128; j++) {
        const ulonglong2* cj = reinterpret_cast<const ulonglong2*>(&cpk[j * 8]);
        ulonglong2 c01 = cj[0], c23 = cj[1], c45 = cj[2], c67 = cj[3];
        u64 acc = 0ull;                 // {+0, +0}; d-sequential fp32 accumulation
        acc = fma2(c01.x, xp[0], acc);
        acc = fma2(c01.y, xp[1], acc);
        acc = fma2(c23.x, xp[2], acc);
        acc = fma2(c23.y, xp[3], acc);
        acc = fma2(c45.x, xp[4], acc);
        acc = fma2(c45.y, xp[5], acc);
        acc = fma2(c67.x, xp[6], acc);
        acc = fma2(c67.y, xp[7], acc);
        float lo, hi;
        unpack2(acc, lo, hi);
        if (lo > bv) { bv = lo; bk = 2 * j; }       // strict >: lowest k wins ties
        if (hi > bv) { bv = hi; bk = 2 * j + 1; }
    }

    // ---- x_hat: one aligned 32B sector per lane (no RMW; merges in L2) ----
    {
        const float4 v0 = craw[bk * 2];
        const float4 v1 = craw[bk * 2 + 1];
        float4* xh = reinterpret_cast<float4*>(xhat) + (size_t)b * (FEAT / 4) + m * 2;
        xh[0] = v0;     // default caching: stays in L2, full-sector write
        xh[1] = v1;
    }

    // ---- fused one-hot stream: 32 rows, each written ONCE, coalesced ----
    // Row r belongs to b0w+r; its winner lives in lane r -> broadcast via shfl.
    {
        float4* crow = reinterpret_cast<float4*>(codes) +
                       ((size_t)b0w * MM + m) * (KK / 4) + lane;
        const int k0 = 4 * lane;          // this lane's first float4 covers k0..k0+3
        const int k1 = 128 + 4 * lane;    // second float4 covers k1..k1+3
#pragma unroll 8
        for (int r = 0; r < 32; r++) {
            const int ok = __shfl_sync(0xffffffffu, bk, r);
            float4 v0, v1;
            v0.x = (k0 + 0 == ok) ? 1.f : 0.f;
            v0.y = (k0 + 1 == ok) ? 1.f : 0.f;
            v0.z = (k0 + 2 == ok) ? 1.f : 0.f;
            v0.w = (k0 + 3 == ok) ? 1.f : 0.f;
            v1.x = (k1 + 0 == ok) ? 1.f : 0.f;
            v1.y = (k1 + 1 == ok) ? 1.f : 0.f;
            v1.z = (k1 + 2 == ok) ? 1.f : 0.f;
            v1.w = (k1 + 3 == ok) ? 1.f : 0.f;
            __stcs(crow, v0);             // streaming: keep 1.07GB out of L2
            __stcs(crow + 32, v1);
            crow += MM * (KK / 4);        // next b, same m
        }
    }
}

extern "C" void kernel_launch(void* const* d_in, const int* in_sizes, int n_in,
                              void* d_out, int out_size)
{
    const float* x = (const float*)d_in[0];
    const float* C = (const float*)d_in[1];
    if (n_in >= 2 && in_sizes[0] == MM * KK * DD && in_sizes[1] == BB * FEAT) {
        x = (const float*)d_in[1];
        C = (const float*)d_in[0];
    }

    const long XHAT_N  = (long)BB * FEAT;        // 8,388,608
    const long CODES_N = (long)BB * MM * KK;     // 268,435,456

    float* xhat  = nullptr;
    float* codes = nullptr;
    if ((long)out_size >= XHAT_N + CODES_N) {
        xhat  = (float*)d_out;
        codes = (float*)d_out + XHAT_N;
    } else if ((long)out_size == CODES_N) {
        codes = (float*)d_out;
    } else {
        xhat = (float*)d_out;
    }

    dim3 grid(MM, BB / CHUNK_B);                 // (64, 64)
    pq_forward_v7<<<grid, 256>>>(x, C, xhat, codes);
}

// round 8
// speedup vs baseline: 1.5898x; 1.0068x over previous
#include <cuda_runtime.h>
#include <cstdint>

// PQLayer forward on GB300 (sm_103a) — v8: v7 + two b's per thread so each
// codebook LDS.128 feeds two FFMA2 chains (L1 was the top pipe at 86.3%).
//
// codes = stop_gradient(hard - soft) + soft == hard (one-hot) numerically.

#define BB 16384
#define MM 64
#define KK 256
#define DD 8
#define FEAT (MM * DD)          // 512
#define CHUNK_B 512             // b per block: 8 warps x 64 b (2 per lane)

using u64 = unsigned long long;

__device__ __forceinline__ u64 pack2(float lo, float hi) {
    u64 r;
    uint32_t a = __float_as_uint(lo), b = __float_as_uint(hi);
    asm("mov.b64 %0, {%1, %2};" : "=l"(r) : "r"(a), "r"(b));
    return r;
}

__device__ __forceinline__ void unpack2(u64 v, float& lo, float& hi) {
    uint32_t a, b;
    asm("mov.b64 {%0, %1}, %2;" : "=r"(a), "=r"(b) : "l"(v));
    lo = __uint_as_float(a);
    hi = __uint_as_float(b);
}

// Packed dual fp32 FMA (Blackwell FFMA2): IEEE fp32 per lane.
__device__ __forceinline__ u64 fma2(u64 a, u64 b, u64 c) {
    u64 r;
    asm("fma.rn.f32x2 %0, %1, %2, %3;" : "=l"(r) : "l"(a), "l"(b), "l"(c));
    return r;
}

__global__ void __launch_bounds__(256)
pq_forward_v8(const float* __restrict__ x, const float* __restrict__ C,
              float* __restrict__ xhat, float* __restrict__ codes)
{
    const int m    = blockIdx.x;
    const int tid  = threadIdx.x;
    const int lane = tid & 31;
    const int w    = tid >> 5;

    // cpk[j*8 + d] = { C[m][2j][d], C[m][2j+1][d] }  (k-pair packed, 8 KB)
    __shared__ __align__(16) u64    cpk[128 * 8];
    __shared__ __align__(16) float4 craw[KK * 2];    // raw copy for x_hat write

    {
        const float4* C4 = reinterpret_cast<const float4*>(C) + (size_t)m * (KK * 2);
#pragma unroll
        for (int q = tid; q < KK * 2; q += 256) {
            float4 f = C4[q];
            craw[q] = f;
            const int k = q >> 1, h = (q & 1) * 4;
            const int j = k >> 1, half = k & 1;
            float vals[4] = {f.x, f.y, f.z, f.w};
#pragma unroll
            for (int dd = 0; dd < 4; dd++)
                reinterpret_cast<uint32_t*>(&cpk[j * 8 + h + dd])[half] =
                    __float_as_uint(vals[dd]);
        }
    }
    __syncthreads();

    const int b0w = blockIdx.y * CHUNK_B + w * 64;   // warp's first b (owns 64)
    const int ba  = b0w + lane;                      // this thread's b #0
    const int bb  = b0w + 32 + lane;                 // this thread's b #1

    // ---- load x for both b's, duplicate-pack for f32x2 ----
    const float4* x4 = reinterpret_cast<const float4*>(x);
    const float4 a0 = x4[(size_t)ba * (FEAT / 4) + m * 2];
    const float4 a1 = x4[(size_t)ba * (FEAT / 4) + m * 2 + 1];
    const float4 q0 = x4[(size_t)bb * (FEAT / 4) + m * 2];
    const float4 q1 = x4[(size_t)bb * (FEAT / 4) + m * 2 + 1];
    u64 xpa[8], xpb[8];
    xpa[0] = pack2(a0.x, a0.x); xpa[1] = pack2(a0.y, a0.y);
    xpa[2] = pack2(a0.z, a0.z); xpa[3] = pack2(a0.w, a0.w);
    xpa[4] = pack2(a1.x, a1.x); xpa[5] = pack2(a1.y, a1.y);
    xpa[6] = pack2(a1.z, a1.z); xpa[7] = pack2(a1.w, a1.w);
    xpb[0] = pack2(q0.x, q0.x); xpb[1] = pack2(q0.y, q0.y);
    xpb[2] = pack2(q0.z, q0.z); xpb[3] = pack2(q0.w, q0.w);
    xpb[4] = pack2(q1.x, q1.x); xpb[5] = pack2(q1.y, q1.y);
    xpb[6] = pack2(q1.z, q1.z); xpb[7] = pack2(q1.w, q1.w);

    // ---- argmax over 256 codewords for BOTH b's: shared LDS stream ----
    float bva = -3.402823466e+38f, bvb = -3.402823466e+38f;
    int   bka = 0, bkb = 0;
#pragma unroll 4
    for (int j = 0; j < 128; j++) {
        const ulonglong2* cj = reinterpret_cast<const ulonglong2*>(&cpk[j * 8]);
        ulonglong2 c01 = cj[0], c23 = cj[1], c45 = cj[2], c67 = cj[3];

        u64 acca = 0ull, accb = 0ull;   // d-sequential fp32 accumulation
        acca = fma2(c01.x, xpa[0], acca);  accb = fma2(c01.x, xpb[0], accb);
        acca = fma2(c01.y, xpa[1], acca);  accb = fma2(c01.y, xpb[1], accb);
        acca = fma2(c23.x, xpa[2], acca);  accb = fma2(c23.x, xpb[2], accb);
        acca = fma2(c23.y, xpa[3], acca);  accb = fma2(c23.y, xpb[3], accb);
        acca = fma2(c45.x, xpa[4], acca);  accb = fma2(c45.x, xpb[4], accb);
        acca = fma2(c45.y, xpa[5], acca);  accb = fma2(c45.y, xpb[5], accb);
        acca = fma2(c67.x, xpa[6], acca);  accb = fma2(c67.x, xpb[6], accb);
        acca = fma2(c67.y, xpa[7], acca);  accb = fma2(c67.y, xpb[7], accb);

        float lo, hi;
        unpack2(acca, lo, hi);
        if (lo > bva) { bva = lo; bka = 2 * j; }     // strict >: lowest k ties
        if (hi > bva) { bva = hi; bka = 2 * j + 1; }
        unpack2(accb, lo, hi);
        if (lo > bvb) { bvb = lo; bkb = 2 * j; }
        if (hi > bvb) { bvb = hi; bkb = 2 * j + 1; }
    }

    // ---- x_hat: one aligned 32B sector per lane per b (no RMW; L2 merge) ----
    {
        float4* xh = reinterpret_cast<float4*>(xhat);
        const float4 va0 = craw[bka * 2], va1 = craw[bka * 2 + 1];
        xh[(size_t)ba * (FEAT / 4) + m * 2]     = va0;
        xh[(size_t)ba * (FEAT / 4) + m * 2 + 1] = va1;
        const float4 vb0 = craw[bkb * 2], vb1 = craw[bkb * 2 + 1];
        xh[(size_t)bb * (FEAT / 4) + m * 2]     = vb0;
        xh[(size_t)bb * (FEAT / 4) + m * 2 + 1] = vb1;
    }

    // ---- fused one-hot stream: 64 rows, each written ONCE, coalesced ----
    // Row r: winner bka of lane r; row r+32: winner bkb of lane r.
    {
        float4* crow = reinterpret_cast<float4*>(codes) +
                       ((size_t)b0w * MM + m) * (KK / 4) + lane;
        const size_t rs = (size_t)MM * (KK / 4);     // row stride (one b)
        const int k0 = 4 * lane;          // first float4 covers k0..k0+3
        const int k1 = 128 + 4 * lane;    // second float4 covers k1..k1+3
#pragma unroll 8
        for (int r = 0; r < 32; r++) {
            const int oa = __shfl_sync(0xffffffffu, bka, r);
            const int ob = __shfl_sync(0xffffffffu, bkb, r);
            float4 v0, v1;
            v0.x = (k0 + 0 == oa) ? 1.f : 0.f;
            v0.y = (k0 + 1 == oa) ? 1.f : 0.f;
            v0.z = (k0 + 2 == oa) ? 1.f : 0.f;
            v0.w = (k0 + 3 == oa) ? 1.f : 0.f;
            v1.x = (k1 + 0 == oa) ? 1.f : 0.f;
            v1.y = (k1 + 1 == oa) ? 1.f : 0.f;
            v1.z = (k1 + 2 == oa) ? 1.f : 0.f;
            v1.w = (k1 + 3 == oa) ? 1.f : 0.f;
            __stcs(crow, v0);             // streaming: keep 1.07GB out of L2
            __stcs(crow + 32, v1);
            v0.x = (k0 + 0 == ob) ? 1.f : 0.f;
            v0.y = (k0 + 1 == ob) ? 1.f : 0.f;
            v0.z = (k0 + 2 == ob) ? 1.f : 0.f;
            v0.w = (k0 + 3 == ob) ? 1.f : 0.f;
            v1.x = (k1 + 0 == ob) ? 1.f : 0.f;
            v1.y = (k1 + 1 == ob) ? 1.f : 0.f;
            v1.z = (k1 + 2 == ob) ? 1.f : 0.f;
            v1.w = (k1 + 3 == ob) ? 1.f : 0.f;
            __stcs(crow + 32 * rs, v0);   // row r+32 (b #1 of lane r)
            __stcs(crow + 32 * rs + 32, v1);
            crow += rs;                   // next b, same m
        }
    }
}

extern "C" void kernel_launch(void* const* d_in, const int* in_sizes, int n_in,
                              void* d_out, int out_size)
{
    const float* x = (const float*)d_in[0];
    const float* C = (const float*)d_in[1];
    if (n_in >= 2 && in_sizes[0] == MM * KK * DD && in_sizes[1] == BB * FEAT) {
        x = (const float*)d_in[1];
        C = (const float*)d_in[0];
    }

    const long XHAT_N  = (long)BB * FEAT;        // 8,388,608
    const long CODES_N = (long)BB * MM * KK;     // 268,435,456

    float* xhat  = nullptr;
    float* codes = nullptr;
    if ((long)out_size >= XHAT_N + CODES_N) {
        xhat  = (float*)d_out;
        codes = (float*)d_out + XHAT_N;
    } else if ((long)out_size == CODES_N) {
        codes = (float*)d_out;
    } else {
        xhat = (float*)d_out;
    }

    dim3 grid(MM, BB / CHUNK_B);                 // (64, 32)
    pq_forward_v8<<<grid, 256>>>(x, C, xhat, codes);
}

// round 9
// speedup vs baseline: 1.6325x; 1.0268x over previous
#include <cuda_runtime.h>
#include <cstdint>

// PQLayer forward on GB300 (sm_103a) — v9: v8 with 128-thread blocks and
// CHUNK_B=256 (8192 blocks) for finer chip-level load balance and more
// resident warps. Algorithm unchanged (R=2, fused one-hot + xhat).
//
// codes = stop_gradient(hard - soft) + soft == hard (one-hot) numerically.

#define BB 16384
#define MM 64
#define KK 256
#define DD 8
#define FEAT (MM * DD)          // 512
#define CHUNK_B 256             // b per block: 4 warps x 64 b (2 per lane)
#define NTHR 128

using u64 = unsigned long long;

__device__ __forceinline__ u64 pack2(float lo, float hi) {
    u64 r;
    uint32_t a = __float_as_uint(lo), b = __float_as_uint(hi);
    asm("mov.b64 %0, {%1, %2};" : "=l"(r) : "r"(a), "r"(b));
    return r;
}

__device__ __forceinline__ void unpack2(u64 v, float& lo, float& hi) {
    uint32_t a, b;
    asm("mov.b64 {%0, %1}, %2;" : "=r"(a), "=r"(b) : "l"(v));
    lo = __uint_as_float(a);
    hi = __uint_as_float(b);
}

// Packed dual fp32 FMA (Blackwell FFMA2): IEEE fp32 per lane.
__device__ __forceinline__ u64 fma2(u64 a, u64 b, u64 c) {
    u64 r;
    asm("fma.rn.f32x2 %0, %1, %2, %3;" : "=l"(r) : "l"(a), "l"(b), "l"(c));
    return r;
}

__global__ void __launch_bounds__(NTHR)
pq_forward_v9(const float* __restrict__ x, const float* __restrict__ C,
              float* __restrict__ xhat, float* __restrict__ codes)
{
    const int m    = blockIdx.x;
    const int tid  = threadIdx.x;
    const int lane = tid & 31;
    const int w    = tid >> 5;

    // cpk[j*8 + d] = { C[m][2j][d], C[m][2j+1][d] }  (k-pair packed, 8 KB)
    __shared__ __align__(16) u64    cpk[128 * 8];
    __shared__ __align__(16) float4 craw[KK * 2];    // raw copy for x_hat write

    {
        const float4* C4 = reinterpret_cast<const float4*>(C) + (size_t)m * (KK * 2);
#pragma unroll
        for (int q = tid; q < KK * 2; q += NTHR) {
            float4 f = C4[q];
            craw[q] = f;
            const int k = q >> 1, h = (q & 1) * 4;
            const int j = k >> 1, half = k & 1;
            float vals[4] = {f.x, f.y, f.z, f.w};
#pragma unroll
            for (int dd = 0; dd < 4; dd++)
                reinterpret_cast<uint32_t*>(&cpk[j * 8 + h + dd])[half] =
                    __float_as_uint(vals[dd]);
        }
    }
    __syncthreads();

    const int b0w = blockIdx.y * CHUNK_B + w * 64;   // warp's first b (owns 64)
    const int ba  = b0w + lane;                      // this thread's b #0
    const int bb  = b0w + 32 + lane;                 // this thread's b #1

    // ---- load x for both b's, duplicate-pack for f32x2 ----
    const float4* x4 = reinterpret_cast<const float4*>(x);
    const float4 a0 = x4[(size_t)ba * (FEAT / 4) + m * 2];
    const float4 a1 = x4[(size_t)ba * (FEAT / 4) + m * 2 + 1];
    const float4 q0 = x4[(size_t)bb * (FEAT / 4) + m * 2];
    const float4 q1 = x4[(size_t)bb * (FEAT / 4) + m * 2 + 1];
    u64 xpa[8], xpb[8];
    xpa[0] = pack2(a0.x, a0.x); xpa[1] = pack2(a0.y, a0.y);
    xpa[2] = pack2(a0.z, a0.z); xpa[3] = pack2(a0.w, a0.w);
    xpa[4] = pack2(a1.x, a1.x); xpa[5] = pack2(a1.y, a1.y);
    xpa[6] = pack2(a1.z, a1.z); xpa[7] = pack2(a1.w, a1.w);
    xpb[0] = pack2(q0.x, q0.x); xpb[1] = pack2(q0.y, q0.y);
    xpb[2] = pack2(q0.z, q0.z); xpb[3] = pack2(q0.w, q0.w);
    xpb[4] = pack2(q1.x, q1.x); xpb[5] = pack2(q1.y, q1.y);
    xpb[6] = pack2(q1.z, q1.z); xpb[7] = pack2(q1.w, q1.w);

    // ---- argmax over 256 codewords for BOTH b's: shared LDS stream ----
    float bva = -3.402823466e+38f, bvb = -3.402823466e+38f;
    int   bka = 0, bkb = 0;
#pragma unroll 4
    for (int j = 0; j < 128; j++) {
        const ulonglong2* cj = reinterpret_cast<const ulonglong2*>(&cpk[j * 8]);
        ulonglong2 c01 = cj[0], c23 = cj[1], c45 = cj[2], c67 = cj[3];

        u64 acca = 0ull, accb = 0ull;   // d-sequential fp32 accumulation
        acca = fma2(c01.x, xpa[0], acca);  accb = fma2(c01.x, xpb[0], accb);
        acca = fma2(c01.y, xpa[1], acca);  accb = fma2(c01.y, xpb[1], accb);
        acca = fma2(c23.x, xpa[2], acca);  accb = fma2(c23.x, xpb[2], accb);
        acca = fma2(c23.y, xpa[3], acca);  accb = fma2(c23.y, xpb[3], accb);
        acca = fma2(c45.x, xpa[4], acca);  accb = fma2(c45.x, xpb[4], accb);
        acca = fma2(c45.y, xpa[5], acca);  accb = fma2(c45.y, xpb[5], accb);
        acca = fma2(c67.x, xpa[6], acca);  accb = fma2(c67.x, xpb[6], accb);
        acca = fma2(c67.y, xpa[7], acca);  accb = fma2(c67.y, xpb[7], accb);

        float lo, hi;
        unpack2(acca, lo, hi);
        if (lo > bva) { bva = lo; bka = 2 * j; }     // strict >: lowest k ties
        if (hi > bva) { bva = hi; bka = 2 * j + 1; }
        unpack2(accb, lo, hi);
        if (lo > bvb) { bvb = lo; bkb = 2 * j; }
        if (hi > bvb) { bvb = hi; bkb = 2 * j + 1; }
    }

    // ---- x_hat: one aligned 32B sector per lane per b (no RMW; L2 merge) ----
    {
        float4* xh = reinterpret_cast<float4*>(xhat);
        const float4 va0 = craw[bka * 2], va1 = craw[bka * 2 + 1];
        xh[(size_t)ba * (FEAT / 4) + m * 2]     = va0;
        xh[(size_t)ba * (FEAT / 4) + m * 2 + 1] = va1;
        const float4 vb0 = craw[bkb * 2], vb1 = craw[bkb * 2 + 1];
        xh[(size_t)bb * (FEAT / 4) + m * 2]     = vb0;
        xh[(size_t)bb * (FEAT / 4) + m * 2 + 1] = vb1;
    }

    // ---- fused one-hot stream: 64 rows, each written ONCE, coalesced ----
    // Row r: winner bka of lane r; row r+32: winner bkb of lane r.
    {
        float4* crow = reinterpret_cast<float4*>(codes) +
                       ((size_t)b0w * MM + m) * (KK / 4) + lane;
        const size_t rs = (size_t)MM * (KK / 4);     // row stride (one b)
        const int k0 = 4 * lane;          // first float4 covers k0..k0+3
        const int k1 = 128 + 4 * lane;    // second float4 covers k1..k1+3
#pragma unroll 8
        for (int r = 0; r < 32; r++) {
            const int oa = __shfl_sync(0xffffffffu, bka, r);
            const int ob = __shfl_sync(0xffffffffu, bkb, r);
            float4 v0, v1;
            v0.x = (k0 + 0 == oa) ? 1.f : 0.f;
            v0.y = (k0 + 1 == oa) ? 1.f : 0.f;
            v0.z = (k0 + 2 == oa) ? 1.f : 0.f;
            v0.w = (k0 + 3 == oa) ? 1.f : 0.f;
            v1.x = (k1 + 0 == oa) ? 1.f : 0.f;
            v1.y = (k1 + 1 == oa) ? 1.f : 0.f;
            v1.z = (k1 + 2 == oa) ? 1.f : 0.f;
            v1.w = (k1 + 3 == oa) ? 1.f : 0.f;
            __stcs(crow, v0);             // streaming: keep 1.07GB out of L2
            __stcs(crow + 32, v1);
            v0.x = (k0 + 0 == ob) ? 1.f : 0.f;
            v0.y = (k0 + 1 == ob) ? 1.f : 0.f;
            v0.z = (k0 + 2 == ob) ? 1.f : 0.f;
            v0.w = (k0 + 3 == ob) ? 1.f : 0.f;
            v1.x = (k1 + 0 == ob) ? 1.f : 0.f;
            v1.y = (k1 + 1 == ob) ? 1.f : 0.f;
            v1.z = (k1 + 2 == ob) ? 1.f : 0.f;
            v1.w = (k1 + 3 == ob) ? 1.f : 0.f;
            __stcs(crow + 32 * rs, v0);   // row r+32 (b #1 of lane r)
            __stcs(crow + 32 * rs + 32, v1);
            crow += rs;                   // next b, same m
        }
    }
}

extern "C" void kernel_launch(void* const* d_in, const int* in_sizes, int n_in,
                              void* d_out, int out_size)
{
    const float* x = (const float*)d_in[0];
    const float* C = (const float*)d_in[1];
    if (n_in >= 2 && in_sizes[0] == MM * KK * DD && in_sizes[1] == BB * FEAT) {
        x = (const float*)d_in[1];
        C = (const float*)d_in[0];
    }

    const long XHAT_N  = (long)BB * FEAT;        // 8,388,608
    const long CODES_N = (long)BB * MM * KK;     // 268,435,456

    float* xhat  = nullptr;
    float* codes = nullptr;
    if ((long)out_size >= XHAT_N + CODES_N) {
        xhat  = (float*)d_out;
        codes = (float*)d_out + XHAT_N;
    } else if ((long)out_size == CODES_N) {
        codes = (float*)d_out;
    } else {
        xhat = (float*)d_out;
    }

    dim3 grid(MM, BB / CHUNK_B);                 // (64, 64) -> 8192 blocks? no: 4096
    pq_forward_v9<<<grid, NTHR>>>(x, C, xhat, codes);
}